// round 1
// baseline (speedup 1.0000x reference)
#include <cuda_runtime.h>
#include <math.h>

#define N_MAX 16384
#define D 16
#define TBLOCK 256
#define T_EVAL 4
#define EVAL_PER_BLOCK (TBLOCK * T_EVAL)   // 1024 eval rows per block
#define NSPLIT 32
#define BTILE 128

// Scratch (no device allocation allowed): per-base constants + split partials.
__device__ float g_cb[N_MAX];
__device__ float g_part[NSPLIT * N_MAX];

// t1 = -0.5*D*log(2*pi) - log(0.1)
#define T1_CONST (-12.400431438280716f)

__global__ void kde_prep_cb(const float* __restrict__ xb, int n) {
    int j = blockIdx.x * blockDim.x + threadIdx.x;
    if (j < n) {
        const float4* r = (const float4*)(xb + (size_t)j * D);
        float s = 0.f;
        #pragma unroll
        for (int q = 0; q < 4; q++) {
            float4 v = r[q];
            s += v.x * v.x + v.y * v.y + v.z * v.z + v.w * v.w;
        }
        g_cb[j] = -50.0f * s;
    }
}

__global__ __launch_bounds__(TBLOCK) void kde_main(const float* __restrict__ xe,
                                                   const float* __restrict__ xb,
                                                   int n) {
    __shared__ float sb[BTILE * D];
    __shared__ float scb[BTILE];

    const int split = blockIdx.y;
    const int base_per_split = n / NSPLIT;
    const int base0 = split * base_per_split;
    const int base1 = base0 + base_per_split;
    const int erow0 = blockIdx.x * EVAL_PER_BLOCK + threadIdx.x * T_EVAL;

    // Load this thread's 4 eval rows, pre-scaled by 100 (so dot accumulates 100*<e,b>),
    // and the per-row constant ce = t1 - 50*||e||^2.
    float se[T_EVAL][D];
    float ce[T_EVAL];
    float acc[T_EVAL];
    #pragma unroll
    for (int t = 0; t < T_EVAL; t++) {
        const float4* r = (const float4*)(xe + (size_t)(erow0 + t) * D);
        float e2 = 0.f;
        #pragma unroll
        for (int q = 0; q < 4; q++) {
            float4 v = r[q];
            e2 += v.x * v.x + v.y * v.y + v.z * v.z + v.w * v.w;
            se[t][4 * q + 0] = 100.f * v.x;
            se[t][4 * q + 1] = 100.f * v.y;
            se[t][4 * q + 2] = 100.f * v.z;
            se[t][4 * q + 3] = 100.f * v.w;
        }
        ce[t] = T1_CONST - 50.f * e2;
        acc[t] = 0.f;
    }

    for (int tb = base0; tb < base1; tb += BTILE) {
        __syncthreads();
        // Stage BTILE base rows (2048 floats) + their cb constants into smem.
        #pragma unroll
        for (int idx = threadIdx.x; idx < BTILE * D / 4; idx += TBLOCK)
            ((float4*)sb)[idx] = ((const float4*)(xb + (size_t)tb * D))[idx];
        if (threadIdx.x < BTILE)
            scb[threadIdx.x] = g_cb[tb + threadIdx.x];
        __syncthreads();

        #pragma unroll 2
        for (int j = 0; j < BTILE; j++) {
            float b[D];
            #pragma unroll
            for (int q = 0; q < 4; q++) {
                float4 v = ((const float4*)(sb + j * D))[q];  // warp-broadcast LDS
                b[4 * q + 0] = v.x; b[4 * q + 1] = v.y;
                b[4 * q + 2] = v.z; b[4 * q + 3] = v.w;
            }
            const float cbj = scb[j];
            #pragma unroll
            for (int t = 0; t < T_EVAL; t++) {
                float s = ce[t] + cbj;              // s = t1 - 50*(e2+b2) + 100*dot (accumulated below)
                #pragma unroll
                for (int k = 0; k < D; k++)
                    s = fmaf(se[t][k], b[k], s);
                // expf underflows to 0 below -87.3; contributions in (-87,-30) are
                // < N*exp(-30)/N = 1e-13 << eps, so this guard is exact.
                if (s > -87.0f)
                    acc[t] += __expf(s);
            }
        }
    }

    #pragma unroll
    for (int t = 0; t < T_EVAL; t++)
        g_part[(size_t)split * n + (erow0 + t)] = acc[t];
}

__global__ void kde_reduce(float* __restrict__ out, int n) {
    int i = blockIdx.x * blockDim.x + threadIdx.x;
    if (i < n) {
        float s = 0.f;
        #pragma unroll
        for (int k = 0; k < NSPLIT; k++)
            s += g_part[(size_t)k * n + i];
        out[i] = logf(1e-8f + s * (1.0f / (float)n));
    }
}

extern "C" void kernel_launch(void* const* d_in, const int* in_sizes, int n_in,
                              void* d_out, int out_size) {
    const float* x_eval = (const float*)d_in[0];
    const float* x_base = (const float*)d_in[1];
    float* out = (float*)d_out;
    const int n = in_sizes[0] / D;   // 16384

    kde_prep_cb<<<(n + 255) / 256, 256>>>(x_base, n);
    dim3 grid(n / EVAL_PER_BLOCK, NSPLIT);
    kde_main<<<grid, TBLOCK>>>(x_eval, x_base, n);
    kde_reduce<<<(n + 255) / 256, 256>>>(out, n);
}